// round 7
// baseline (speedup 1.0000x reference)
#include <cuda_runtime.h>
#include <math.h>
#include <stdint.h>

#define Bsz 2
#define Sq  2048
#define Dm  1024
#define Hn  8
#define NEGV (-1e10f)

// Scratch (device globals; no allocations allowed)
__device__ float g_xr[Bsz * Sq * Dm];       // tf32-rounded x
__device__ float g_q[Bsz * Sq * Dm];        // q (tf32-rounded)
__device__ float g_qT[Bsz * Sq * Dm];       // q transposed per batch [D][S]
__device__ float g_scores[Bsz * Sq * Sq];   // scores / probs
__device__ float g_head[Bsz * Sq * Dm];     // head ; later ffn act
__device__ float g_h[Bsz * Sq * Dm];        // h
__device__ float g_weffT[Dm * Dm];          // folded+transposed out_kernel
__device__ float g_wiT[Dm * Dm];            // wi transposed

// ---------------- helpers ----------------
__device__ __forceinline__ float tf32r(float x) {
    uint32_t u;
    asm("cvt.rna.tf32.f32 %0, %1;" : "=r"(u) : "f"(x));
    return __uint_as_float(u);
}
__device__ __forceinline__ uint32_t smem_u32(const void* p) {
    uint32_t a;
    asm("{ .reg .u64 t; cvta.to.shared.u64 t, %1; cvt.u32.u64 %0, t; }" : "=r"(a) : "l"(p));
    return a;
}
#define CPA(d, s)  asm volatile("cp.async.cg.shared.global [%0], [%1], 16;" :: "r"(d), "l"(s) : "memory")
#define CPC()      asm volatile("cp.async.commit_group;" ::: "memory")
#define CPW(n)     asm volatile("cp.async.wait_group %0;" :: "n"(n) : "memory")
#define LDSM4(r0, r1, r2, r3, a) \
    asm volatile("ldmatrix.sync.aligned.m8n8.x4.shared.b16 {%0,%1,%2,%3}, [%4];" \
        : "=r"(r0), "=r"(r1), "=r"(r2), "=r"(r3) : "r"(a))

// ---------------------------------------------------------------------------
// tf32 mma.sync GEMM, 4-stage cp.async pipeline, ldmatrix fragment feed.
// C[M,N] = epi(A[M,K] @ B^T), B stored [N][K] row-major (all operands NT).
// Smem stage layout: 128 rows x 64B (16 tf32); physChunk = chunk ^ ((row>>1)&3).
// Inner loop: ALL 12 LDSM (both k8-steps) issued before ALL 32 MMAs, so only
// the first LDSM group gates the tensor burst.
// EPI: 0 plain | 1 scale+causal | 2 +residual | 3 +bias | 4 swish
// CK: truncate K at (blockRow+1)*128.  RND: tf32-round stored output.
// ---------------------------------------------------------------------------
#define TILE 128
#define BKk  16
#define ASZ  8192
#define NSTG 4
#define DSMEM (2 * NSTG * ASZ)

template <int EPI, bool CK, bool RND>
__global__ __launch_bounds__(256, 2)
void tgemm(const float* __restrict__ A, const float* __restrict__ B,
           float* __restrict__ C, int M, int N, int K,
           long sA, long sB, long sC, float alpha,
           const float* __restrict__ bias, const float* __restrict__ resid, long sR)
{
    if (EPI == 1 && blockIdx.x > blockIdx.y) return;
    const int bz = blockIdx.z;
    A += (size_t)bz * sA;  B += (size_t)bz * sB;  C += (size_t)bz * sC;
    const int m0 = blockIdx.y * TILE;
    const int n0 = blockIdx.x * TILE;
    const int Keff = CK ? min(K, (int)(blockIdx.y + 1) * TILE) : K;
    const int NK = Keff / BKk;

    extern __shared__ char smb[];
    const uint32_t smA = smem_u32(smb);
    const uint32_t smB = smA + NSTG * ASZ;

    const int t    = threadIdx.x;
    const int lane = t & 31;
    const int wid  = t >> 5;
    const int wRow = wid >> 2;        // 0..1
    const int wCol = wid & 3;         // 0..3

    const int lrow  = t >> 2;
    const int lchnk = t & 3;

    auto load_stage = [&](int s, int kc) {
        const uint32_t da = smA + s * ASZ;
        const uint32_t db = smB + s * ASZ;
#pragma unroll
        for (int r = 0; r < 2; r++) {
            const int row  = lrow + r * 64;
            const int phys = lchnk ^ ((row >> 1) & 3);
            CPA(da + row * 64 + phys * 16,
                A + (size_t)(m0 + row) * K + kc * BKk + lchnk * 4);
            CPA(db + row * 64 + phys * 16,
                B + (size_t)(n0 + row) * K + kc * BKk + lchnk * 4);
        }
    };

    // ldmatrix per-lane source rows / chunk-halves (loop-invariant)
    const int aRowOff = (lane & 7) + ((lane >> 3) & 1) * 8;
    const int aChHalf = lane >> 4;
    const int bRowOff = ((lane >> 4) & 1) * 8 + (lane & 7);
    const int bChHalf = (lane >> 3) & 1;

    // Precompute lane-constant smem offsets (stage base added per iter)
    uint32_t aOff[2][4], bOff[2][2];
#pragma unroll
    for (int kk = 0; kk < 2; kk++) {
#pragma unroll
        for (int mt = 0; mt < 4; mt++) {
            const int row   = wRow * 64 + mt * 16 + aRowOff;
            const int chunk = kk * 2 + aChHalf;
            aOff[kk][mt] = row * 64 + ((chunk ^ ((row >> 1) & 3)) << 4);
        }
#pragma unroll
        for (int p = 0; p < 2; p++) {
            const int row   = wCol * 32 + p * 16 + bRowOff;
            const int chunk = kk * 2 + bChHalf;
            bOff[kk][p] = row * 64 + ((chunk ^ ((row >> 1) & 3)) << 4);
        }
    }

    float acc[4][4][4];
#pragma unroll
    for (int i = 0; i < 4; i++)
#pragma unroll
        for (int j = 0; j < 4; j++)
#pragma unroll
            for (int e = 0; e < 4; e++) acc[i][j][e] = 0.f;

#pragma unroll
    for (int s = 0; s < NSTG - 1; s++) { load_stage(s, s); CPC(); }

    for (int it = 0; it < NK; it++) {
        CPW(2);
        __syncthreads();
        if (it + NSTG - 1 < NK) load_stage((it + NSTG - 1) & (NSTG - 1), it + NSTG - 1);
        CPC();

        const int s = it & (NSTG - 1);
        const uint32_t aBase = smA + s * ASZ;
        const uint32_t bBase = smB + s * ASZ;

        // ---- all fragment loads first (12 LDSM) ----
        uint32_t af[2][4][4], bf[2][4][2];
#pragma unroll
        for (int kk = 0; kk < 2; kk++) {
#pragma unroll
            for (int mt = 0; mt < 4; mt++)
                LDSM4(af[kk][mt][0], af[kk][mt][1], af[kk][mt][2], af[kk][mt][3],
                      aBase + aOff[kk][mt]);
#pragma unroll
            for (int p = 0; p < 2; p++)
                LDSM4(bf[kk][2 * p][0], bf[kk][2 * p][1],
                      bf[kk][2 * p + 1][0], bf[kk][2 * p + 1][1],
                      bBase + bOff[kk][p]);
        }

        // ---- then the 32-MMA burst ----
#pragma unroll
        for (int kk = 0; kk < 2; kk++)
#pragma unroll
            for (int mt = 0; mt < 4; mt++)
#pragma unroll
                for (int nt = 0; nt < 4; nt++) {
                    float* d = acc[mt][nt];
                    asm volatile(
                        "mma.sync.aligned.m16n8k8.row.col.f32.tf32.tf32.f32 "
                        "{%0,%1,%2,%3}, {%4,%5,%6,%7}, {%8,%9}, {%0,%1,%2,%3};"
                        : "+f"(d[0]), "+f"(d[1]), "+f"(d[2]), "+f"(d[3])
                        : "r"(af[kk][mt][0]), "r"(af[kk][mt][1]),
                          "r"(af[kk][mt][2]), "r"(af[kk][mt][3]),
                          "r"(bf[kk][nt][0]), "r"(bf[kk][nt][1]));
                }
    }

    // ---- epilogue ----
    const int g = lane >> 2;
    const int c = lane & 3;
#pragma unroll
    for (int mt = 0; mt < 4; mt++) {
#pragma unroll
        for (int nt = 0; nt < 4; nt++) {
            const int row0 = m0 + wRow * 64 + mt * 16 + g;
            const int col0 = n0 + wCol * 32 + nt * 8 + 2 * c;
            float* d = acc[mt][nt];
#pragma unroll
            for (int half = 0; half < 2; half++) {
                const int row = row0 + half * 8;
                float v0 = d[half * 2 + 0];
                float v1 = d[half * 2 + 1];
                if (EPI == 1) {
                    v0 = (col0 <= row)     ? v0 * alpha : NEGV;
                    v1 = (col0 + 1 <= row) ? v1 * alpha : NEGV;
                }
                if (EPI == 2) {
                    const float* rr = resid + (size_t)bz * sR + (size_t)row * N + col0;
                    v0 += rr[0]; v1 += rr[1];
                }
                if (EPI == 3) { v0 += bias[col0]; v1 += bias[col0 + 1]; }
                if (EPI == 4) {
                    v0 = v0 / (1.f + __expf(-v0));
                    v1 = v1 / (1.f + __expf(-v1));
                }
                if (RND) { v0 = tf32r(v0); v1 = tf32r(v1); }
                *(float2*)&C[(size_t)row * N + col0] = make_float2(v0, v1);
            }
        }
    }
}

// ---------------------------------------------------------------------------
__global__ void round_copy(const float* __restrict__ in, float* __restrict__ out) {
    const int i = (blockIdx.x * 256 + threadIdx.x) * 4;
    float4 v = *(const float4*)(in + i);
    v.x = tf32r(v.x); v.y = tf32r(v.y); v.z = tf32r(v.z); v.w = tf32r(v.w);
    *(float4*)(out + i) = v;
}

__global__ void transpose_b(const float* __restrict__ in, float* __restrict__ out,
                            int R, int C, long sI, long sO) {
    __shared__ float tile[32][33];
    const float* I = in  + (size_t)blockIdx.z * sI;
    float*       O = out + (size_t)blockIdx.z * sO;
    const int r0 = blockIdx.y * 32, c0 = blockIdx.x * 32;
    const int tx = threadIdx.x, ty = threadIdx.y;
#pragma unroll
    for (int j = 0; j < 4; j++)
        tile[ty + j * 8][tx] = tf32r(I[(size_t)(r0 + ty + j * 8) * C + c0 + tx]);
    __syncthreads();
#pragma unroll
    for (int j = 0; j < 4; j++)
        O[(size_t)(c0 + ty + j * 8) * R + r0 + tx] = tile[tx][ty + j * 8];
}

__global__ void fold_transpose(const float* __restrict__ ok, float* __restrict__ out) {
    __shared__ float tile[32][33];
    const int k0 = blockIdx.x * 32, n0 = blockIdx.y * 32;
    const int tx = threadIdx.x, ty = threadIdx.y;
    float acc[4] = {0.f, 0.f, 0.f, 0.f};
    for (int h = 0; h < Hn; h++)
#pragma unroll
        for (int j = 0; j < 4; j++)
            acc[j] += ok[(size_t)h * Dm * Dm + (size_t)(k0 + ty + 8 * j) * Dm + n0 + tx];
#pragma unroll
    for (int j = 0; j < 4; j++) tile[ty + 8 * j][tx] = tf32r(acc[j]);
    __syncthreads();
#pragma unroll
    for (int j = 0; j < 4; j++)
        out[(size_t)(n0 + ty + 8 * j) * Dm + k0 + tx] = tile[tx][ty + 8 * j];
}

// ---------------------------------------------------------------------------
__global__ void softmax_rows(float* __restrict__ sc) {
    const int rowg = blockIdx.x;
    const int b = rowg / Sq, r = rowg % Sq;
    float* p = sc + (size_t)b * Sq * Sq + (size_t)r * Sq;
    const int L = ((r >> 7) + 1) << 7;
    const int t = threadIdx.x;

    float vals[8];
    int cnt = 0;
    float mx = -INFINITY;
    for (int j = t; j < L; j += 256) { float v = p[j]; vals[cnt++] = v; mx = fmaxf(mx, v); }

    __shared__ float red[256];
    red[t] = mx; __syncthreads();
    for (int s = 128; s > 0; s >>= 1) { if (t < s) red[t] = fmaxf(red[t], red[t + s]); __syncthreads(); }
    mx = red[0]; __syncthreads();

    float sum = 0.f;
    for (int i = 0; i < cnt; i++) { vals[i] = __expf(vals[i] - mx); sum += vals[i]; }
    red[t] = sum; __syncthreads();
    for (int s = 128; s > 0; s >>= 1) { if (t < s) red[t] += red[t + s]; __syncthreads(); }
    const float inv = 1.f / red[0];

    cnt = 0;
    for (int j = t; j < L; j += 256) p[j] = tf32r(vals[cnt++] * inv);
}

__global__ void layernorm_rows(float* __restrict__ h) {
    const int row = blockIdx.x;
    float* p = h + (size_t)row * Dm;
    const int t = threadIdx.x;
    float4 v = *(float4*)&p[t * 4];
    float s  = v.x + v.y + v.z + v.w;
    float sq = v.x * v.x + v.y * v.y + v.z * v.z + v.w * v.w;

    __shared__ float rs[256], rq[256];
    rs[t] = s; rq[t] = sq; __syncthreads();
    for (int k = 128; k > 0; k >>= 1) {
        if (t < k) { rs[t] += rs[t + k]; rq[t] += rq[t + k]; }
        __syncthreads();
    }
    const float mean = rs[0] * (1.f / Dm);
    const float var  = rq[0] * (1.f / Dm) - mean * mean;
    const float inv  = rsqrtf(var + 1e-5f);
    v.x = tf32r((v.x - mean) * inv);
    v.y = tf32r((v.y - mean) * inv);
    v.z = tf32r((v.z - mean) * inv);
    v.w = tf32r((v.w - mean) * inv);
    *(float4*)&p[t * 4] = v;
}

// ---------------------------------------------------------------------------
extern "C" void kernel_launch(void* const* d_in, const int* in_sizes, int n_in,
                              void* d_out, int out_size)
{
    const float* x  = (const float*)d_in[0];
    const float* wi = (const float*)d_in[2];
    const float* ok = (const float*)d_in[3];
    const float* ob = (const float*)d_in[4];
    float* out = (float*)d_out;

    float *xr, *q, *qT, *sc, *head, *h, *weffT, *wiT;
    cudaGetSymbolAddress((void**)&xr,    g_xr);
    cudaGetSymbolAddress((void**)&q,     g_q);
    cudaGetSymbolAddress((void**)&qT,    g_qT);
    cudaGetSymbolAddress((void**)&sc,    g_scores);
    cudaGetSymbolAddress((void**)&head,  g_head);
    cudaGetSymbolAddress((void**)&h,     g_h);
    cudaGetSymbolAddress((void**)&weffT, g_weffT);
    cudaGetSymbolAddress((void**)&wiT,   g_wiT);

    cudaFuncSetAttribute(tgemm<0, false, true>,  cudaFuncAttributeMaxDynamicSharedMemorySize, DSMEM);
    cudaFuncSetAttribute(tgemm<1, false, false>, cudaFuncAttributeMaxDynamicSharedMemorySize, DSMEM);
    cudaFuncSetAttribute(tgemm<2, true,  true>,  cudaFuncAttributeMaxDynamicSharedMemorySize, DSMEM);
    cudaFuncSetAttribute(tgemm<3, false, false>, cudaFuncAttributeMaxDynamicSharedMemorySize, DSMEM);
    cudaFuncSetAttribute(tgemm<4, false, true>,  cudaFuncAttributeMaxDynamicSharedMemorySize, DSMEM);
    cudaFuncSetAttribute(tgemm<0, false, false>, cudaFuncAttributeMaxDynamicSharedMemorySize, DSMEM);

    const int MS = Bsz * Sq;            // 4096
    const long sQ  = (long)Sq * Dm;
    const long sSS = (long)Sq * Sq;

    round_copy<<<(Bsz * Sq * Dm) / 1024, 256>>>(x, xr);
    fold_transpose<<<dim3(Dm / 32, Dm / 32), dim3(32, 8)>>>(ok, weffT);
    transpose_b<<<dim3(Dm / 32, Dm / 32, 1), dim3(32, 8)>>>(wi, wiT, Dm, Dm, 0, 0);

    // q = x @ wi (rounded output)
    tgemm<0, false, true><<<dim3(Dm / TILE, MS / TILE, 1), 256, DSMEM>>>(
        xr, wiT, q, MS, Dm, Dm, 0, 0, 0, 0.f, nullptr, nullptr, 0);

    transpose_b<<<dim3(Dm / 32, Sq / 32, Bsz), dim3(32, 8)>>>(q, qT, Sq, Dm, sQ, sQ);

    // scores = (q @ q^T)/32 causal
    tgemm<1, false, false><<<dim3(Sq / TILE, Sq / TILE, Bsz), 256, DSMEM>>>(
        q, q, sc, Sq, Sq, Dm, sQ, sQ, sSS, 1.f / 32.f, nullptr, nullptr, 0);

    softmax_rows<<<Bsz * Sq, 256>>>(sc);

    // head = P @ q + q
    tgemm<2, true, true><<<dim3(Dm / TILE, Sq / TILE, Bsz), 256, DSMEM>>>(
        sc, qT, head, Sq, Dm, Sq, sSS, sQ, sQ, 0.f, nullptr, q, sQ);

    // h = head @ Weff + bias
    tgemm<3, false, false><<<dim3(Dm / TILE, MS / TILE, 1), 256, DSMEM>>>(
        head, weffT, h, MS, Dm, Dm, 0, 0, 0, 0.f, ob, nullptr, 0);

    layernorm_rows<<<Bsz * Sq, 256>>>(h);

    // act = swish(h @ wi)
    tgemm<4, false, true><<<dim3(Dm / TILE, MS / TILE, 1), 256, DSMEM>>>(
        h, wiT, head, MS, Dm, Dm, 0, 0, 0, 0.f, nullptr, nullptr, 0);

    // out = act @ wi
    tgemm<0, false, false><<<dim3(Dm / TILE, MS / TILE, 1), 256, DSMEM>>>(
        head, wiT, out, MS, Dm, Dm, 0, 0, 0, 0.f, nullptr, nullptr, 0);
}